// round 8
// baseline (speedup 1.0000x reference)
#include <cuda_runtime.h>

// Dynamics_individual (MAK), N=8192, B=R=F=1
// d_in[0]=t (unused), d_in[1]=x [N], d_in[2]=A [N,N]
// d_out = [ f_self (N) | f_nbr (N*N) ], f_self[i]=1-x[i], f_nbr[i][j]=-x[i]*A[i][j]*x[j]
//
// Hybrid 256-bit streaming: v8 (32B) loads of A and v8 stores of f_nbr carry
// the DRAM streams (fewer LSU issues / L1tex queue slots per byte); xj comes
// from L1-resident float4 loads interleaved with compute (R4's regression was
// the 16 scalar x-loads per thread, not the v8 ops). Block = half row, so the
// row index (and s = -x[i]) is uniform per block. 2 octs/thread, MLP=2x1KB/warp.

#define NDIM 8192u
#define TPB 256u
#define OCTS_PER_ROW 1024u       // 8192 / 8
#define OCTS_PER_BLOCK 512u      // half a row; 2 octs per thread

__device__ __forceinline__ void ldg256_cs(const float* p, float v[8]) {
    asm volatile(
        "ld.global.cs.v8.f32 {%0,%1,%2,%3,%4,%5,%6,%7}, [%8];"
        : "=f"(v[0]), "=f"(v[1]), "=f"(v[2]), "=f"(v[3]),
          "=f"(v[4]), "=f"(v[5]), "=f"(v[6]), "=f"(v[7])
        : "l"(p));
}

__device__ __forceinline__ void stg256_cs(float* p, const float v[8]) {
    asm volatile(
        "st.global.cs.v8.f32 [%0], {%1,%2,%3,%4,%5,%6,%7,%8};"
        :: "l"(p),
           "f"(v[0]), "f"(v[1]), "f"(v[2]), "f"(v[3]),
           "f"(v[4]), "f"(v[5]), "f"(v[6]), "f"(v[7])
        : "memory");
}

__global__ void __launch_bounds__(256) dyn_mak_kernel(
    const float* __restrict__ x,
    const float* __restrict__ A,
    float* __restrict__ out)
{
    const unsigned i = blockIdx.x >> 1;                    // row, uniform per block
    const unsigned half = (blockIdx.x & 1u) * OCTS_PER_BLOCK;
    const unsigned c0 = half + threadIdx.x;                // col oct 0
    const unsigned c1 = c0 + TPB;                          // col oct 1
    const unsigned o0 = i * OCTS_PER_ROW + c0;             // global oct 0
    const unsigned o1 = i * OCTS_PER_ROW + c1;             // global oct 1

    const float4* __restrict__ x4 = reinterpret_cast<const float4*>(x);
    float* __restrict__ fnbr = out + NDIM;

    const float s = -__ldg(&x[i]);                         // uniform scalar

    // Front-batched DRAM loads: 2 x 256-bit per thread (16 lines/warp in flight).
    float a0[8], a1[8];
    ldg256_cs(A + (size_t)o0 * 8u, a0);
    ldg256_cs(A + (size_t)o1 * 8u, a1);

    // xj via L1-resident float4s, interleaved with compute (caps live regs).
    {
        float4 xq = x4[c0 * 2u];
        a0[0] = s * a0[0] * xq.x;  a0[1] = s * a0[1] * xq.y;
        a0[2] = s * a0[2] * xq.z;  a0[3] = s * a0[3] * xq.w;
        xq = x4[c0 * 2u + 1u];
        a0[4] = s * a0[4] * xq.x;  a0[5] = s * a0[5] * xq.y;
        a0[6] = s * a0[6] * xq.z;  a0[7] = s * a0[7] * xq.w;
    }
    stg256_cs(fnbr + (size_t)o0 * 8u, a0);

    {
        float4 xq = x4[c1 * 2u];
        a1[0] = s * a1[0] * xq.x;  a1[1] = s * a1[1] * xq.y;
        a1[2] = s * a1[2] * xq.z;  a1[3] = s * a1[3] * xq.w;
        xq = x4[c1 * 2u + 1u];
        a1[4] = s * a1[4] * xq.x;  a1[5] = s * a1[5] * xq.y;
        a1[6] = s * a1[6] * xq.z;  a1[7] = s * a1[7] * xq.w;
    }
    stg256_cs(fnbr + (size_t)o1 * 8u, a1);

    // f_self = 1 - x : first 1024 octs of x-space, blocks 0 and 1.
    if (blockIdx.x < 2) {
        float fs0[8], fs1[8];
#pragma unroll
        for (int k = 0; k < 2; k++) {
            const unsigned c = (k == 0) ? c0 : c1;
            float* fs = (k == 0) ? fs0 : fs1;
            float4 xa = x4[c * 2u];
            float4 xb = x4[c * 2u + 1u];
            fs[0] = 1.0f - xa.x; fs[1] = 1.0f - xa.y;
            fs[2] = 1.0f - xa.z; fs[3] = 1.0f - xa.w;
            fs[4] = 1.0f - xb.x; fs[5] = 1.0f - xb.y;
            fs[6] = 1.0f - xb.z; fs[7] = 1.0f - xb.w;
        }
        stg256_cs(out + (size_t)c0 * 8u, fs0);
        stg256_cs(out + (size_t)c1 * 8u, fs1);
    }
}

extern "C" void kernel_launch(void* const* d_in, const int* in_sizes, int n_in,
                              void* d_out, int out_size)
{
    (void)in_sizes; (void)n_in; (void)out_size;
    const float* x = (const float*)d_in[1];
    const float* A = (const float*)d_in[2];
    float* out = (float*)d_out;

    const unsigned blocks = NDIM * 2u;    // 16384 half-row blocks
    dyn_mak_kernel<<<blocks, TPB>>>(x, A, out);
}

// round 9
// speedup vs baseline: 1.0019x; 1.0019x over previous
#include <cuda_runtime.h>

// Dynamics_individual (MAK), N=8192, B=R=F=1
// d_in[0]=t (unused), d_in[1]=x [N], d_in[2]=A [N,N]
// d_out = [ f_self (N) | f_nbr (N*N) ], f_self[i]=1-x[i], f_nbr[i][j]=-x[i]*A[i][j]*x[j]
//
// FINAL (converged): traffic is compulsory 256MB read + 256MB write with zero
// reuse; every well-shaped config pins at ~6.4 TB/s (80% of spec), the B300
// interleaved read+write DRAM ceiling. This is the best-measured config:
// one block == one full row (2048 float4 quads), TPB=512, 4 front-batched
// LDG.128 per thread (MLP=4), streaming .cs hints both directions, regs=32.

#define NDIM 8192u
#define QUADS_PER_ROW 2048u      // N/4
#define TPB 512u
#define QPT 4u                   // quads per thread (TPB*QPT == QUADS_PER_ROW)

__global__ void __launch_bounds__(512) dyn_mak_kernel(
    const float* __restrict__ x,
    const float* __restrict__ A,
    float* __restrict__ out)
{
    const unsigned i = blockIdx.x;                       // row, uniform per block
    const unsigned base = i * QUADS_PER_ROW + threadIdx.x;

    const float4* __restrict__ A4 = reinterpret_cast<const float4*>(A);
    const float4* __restrict__ x4 = reinterpret_cast<const float4*>(x);
    float4* __restrict__ fnbr = reinterpret_cast<float4*>(out + NDIM);

    const float s = -__ldg(&x[i]);

    // Front-batched: 4 independent LDG.128 in flight per thread.
    float4 a[QPT];
#pragma unroll
    for (int k = 0; k < (int)QPT; k++)
        a[k] = __ldcs(&A4[base + (unsigned)k * TPB]);

#pragma unroll
    for (int k = 0; k < (int)QPT; k++) {
        const unsigned j4 = threadIdx.x + (unsigned)k * TPB;  // col quad in row
        const float4 xj = x4[j4];                             // L1-resident 8 KB
        float4 r;
        r.x = s * a[k].x * xj.x;
        r.y = s * a[k].y * xj.y;
        r.z = s * a[k].z * xj.z;
        r.w = s * a[k].w * xj.w;
        __stcs(&fnbr[base + (unsigned)k * TPB], r);
    }

    // f_self = 1 - x : 2048 quads, exactly block 0's per-row quad range.
    if (i == 0) {
#pragma unroll
        for (int k = 0; k < (int)QPT; k++) {
            const unsigned q = threadIdx.x + (unsigned)k * TPB;
            const float4 xv = x4[q];
            float4 fs;
            fs.x = 1.0f - xv.x;
            fs.y = 1.0f - xv.y;
            fs.z = 1.0f - xv.z;
            fs.w = 1.0f - xv.w;
            reinterpret_cast<float4*>(out)[q] = fs;
        }
    }
}

extern "C" void kernel_launch(void* const* d_in, const int* in_sizes, int n_in,
                              void* d_out, int out_size)
{
    (void)in_sizes; (void)n_in; (void)out_size;
    const float* x = (const float*)d_in[1];
    const float* A = (const float*)d_in[2];
    float* out = (float*)d_out;

    dyn_mak_kernel<<<NDIM, TPB>>>(x, A, out);   // 8192 blocks, one row each
}

// round 10
// speedup vs baseline: 1.0051x; 1.0031x over previous
#include <cuda_runtime.h>

// Dynamics_individual (MAK), N=8192, B=R=F=1
// d_in[0]=t (unused), d_in[1]=x [N], d_in[2]=A [N,N]
// d_out = [ f_self (N) | f_nbr (N*N) ], f_self[i]=1-x[i], f_nbr[i][j]=-x[i]*A[i][j]*x[j]
//
// FINAL (converged): compulsory 256MB read + 256MB write, zero reuse. All
// well-shaped configs pin at 6.3-6.4 TB/s = the B300 interleaved r+w DRAM
// ceiling. This config measured the session-best DRAM% (80.8, 6405 GB/s) and
// occupancy (83.9%): TPB=256, block = half row (row index uniform per block),
// QPT=4 front-batched LDG.128 (MLP=4), .cs streaming hints both ways, regs=32.

#define NDIM 8192u
#define QUADS_PER_ROW 2048u          // N/4
#define TPB 256u
#define QPT 4u
#define QUADS_PER_BLOCK (TPB * QPT)  // 1024 = half a row

__global__ void __launch_bounds__(256) dyn_mak_kernel(
    const float* __restrict__ x,
    const float* __restrict__ A,
    float* __restrict__ out)
{
    const unsigned i = blockIdx.x >> 1;                   // row, uniform per block
    const unsigned half = (blockIdx.x & 1u) * QUADS_PER_BLOCK;
    const unsigned base = i * QUADS_PER_ROW + half + threadIdx.x;

    const float4* __restrict__ A4 = reinterpret_cast<const float4*>(A);
    const float4* __restrict__ x4 = reinterpret_cast<const float4*>(x);
    float4* __restrict__ fnbr = reinterpret_cast<float4*>(out + NDIM);

    const float s = -__ldg(&x[i]);                        // uniform scalar

    // Front-batched: 4 independent LDG.128 in flight per thread.
    float4 a[QPT];
#pragma unroll
    for (int k = 0; k < (int)QPT; k++)
        a[k] = __ldcs(&A4[base + (unsigned)k * TPB]);

#pragma unroll
    for (int k = 0; k < (int)QPT; k++) {
        const unsigned j4 = half + threadIdx.x + (unsigned)k * TPB; // col quad
        const float4 xj = x4[j4];                                   // L1-resident
        float4 r;
        r.x = s * a[k].x * xj.x;
        r.y = s * a[k].y * xj.y;
        r.z = s * a[k].z * xj.z;
        r.w = s * a[k].w * xj.w;
        __stcs(&fnbr[base + (unsigned)k * TPB], r);
    }

    // f_self = 1 - x : 2048 quads, handled by blocks 0 and 1 (first row).
    if (blockIdx.x < 2) {
#pragma unroll
        for (int k = 0; k < (int)QPT; k++) {
            const unsigned q = half + threadIdx.x + (unsigned)k * TPB;
            const float4 xv = x4[q];
            float4 fs;
            fs.x = 1.0f - xv.x;
            fs.y = 1.0f - xv.y;
            fs.z = 1.0f - xv.z;
            fs.w = 1.0f - xv.w;
            reinterpret_cast<float4*>(out)[q] = fs;
        }
    }
}

extern "C" void kernel_launch(void* const* d_in, const int* in_sizes, int n_in,
                              void* d_out, int out_size)
{
    (void)in_sizes; (void)n_in; (void)out_size;
    const float* x = (const float*)d_in[1];
    const float* A = (const float*)d_in[2];
    float* out = (float*)d_out;

    const unsigned blocks = NDIM * 2u;   // two half-row blocks per row = 16384
    dyn_mak_kernel<<<blocks, TPB>>>(x, A, out);
}